// round 15
// baseline (speedup 1.0000x reference)
#include <cuda_runtime.h>
#include <cuda_fp16.h>
#include <cstdint>

// Problem constants: B=8, T=1024, C=768, H=12, HD=64
// All scratch in fp16 (half) except softmax stats.
__device__ __half g_q[6291456];          // [96][1024][64]
__device__ __half g_k[6291456];
__device__ __half g_v[6291456];
__device__ __half g_y[6291456];          // [8192][768]
__device__ __half g_x[6291456];          // [8192][768]
__device__ uint32_t g_wa_p[884736];      // packed w_attn [k2=384][2304]
__device__ uint32_t g_wp_p[294912];      // packed w_proj [k2=384][768]

// ---------------------------------------------------------------------------
// helpers
// ---------------------------------------------------------------------------
__device__ __forceinline__ void mma_f16(float* c, const uint32_t* a, const uint32_t* b) {
    asm volatile(
        "mma.sync.aligned.m16n8k16.row.col.f32.f16.f16.f32 "
        "{%0,%1,%2,%3},{%4,%5,%6,%7},{%8,%9},{%0,%1,%2,%3};"
        : "+f"(c[0]), "+f"(c[1]), "+f"(c[2]), "+f"(c[3])
        : "r"(a[0]), "r"(a[1]), "r"(a[2]), "r"(a[3]), "r"(b[0]), "r"(b[1]));
}
__device__ __forceinline__ uint32_t smem_u32(const void* p) {
    return (uint32_t)__cvta_generic_to_shared(p);
}
__device__ __forceinline__ uint32_t packh2(float a, float b) {
    __half2 h = __floats2half2_rn(a, b);
    return *(uint32_t*)&h;
}
#define CP_ASYNC16(dst, src) \
    asm volatile("cp.async.cg.shared.global [%0], [%1], 16;\n" :: "r"(dst), "l"(src))
#define CP_COMMIT() asm volatile("cp.async.commit_group;\n")
#define CP_WAIT(N)  asm volatile("cp.async.wait_group %0;\n" :: "n"(N))

// ---------------------------------------------------------------------------
// Kernel 0a: x (float) -> g_x (half).
// ---------------------------------------------------------------------------
__global__ __launch_bounds__(256) void conv_x(const float* __restrict__ x)
{
    long i = (long)blockIdx.x * 256 + threadIdx.x;   // 1572864 float4s
    float4 v = ((const float4*)x)[i];
    uint2 o;
    o.x = packh2(v.x, v.y);
    o.y = packh2(v.z, v.w);
    ((uint2*)g_x)[i] = o;
}

// ---------------------------------------------------------------------------
// Kernel 0b: pack weights: dst[k2*N + n] = half2(w[2k2][n], w[2k2+1][n]).
// Destination selected IN-KERNEL (device symbols must not cross host ABI).
// ---------------------------------------------------------------------------
__global__ __launch_bounds__(256) void pack_w(
    const float* __restrict__ src, int N, int which)
{
    uint32_t* dst = which ? g_wp_p : g_wa_p;
    int idx = blockIdx.x * 256 + threadIdx.x;
    int k2 = idx / N, n = idx - k2 * N;
    float a = src[(size_t)(2 * k2) * N + n];
    float b = src[(size_t)(2 * k2 + 1) * N + n];
    dst[idx] = packh2(a, b);
}

// ---------------------------------------------------------------------------
// FP16 GEMM core (R13 proven): block tile 128x128, 8 warps (2m x 4n),
// warp tile 64x32, K-step 32 halfs, 24 steps, 3-stage cp.async, 1 sync/step.
//   As uint32 [3][128][20], Bs uint32 [3][16][136].  Dyn smem 56832B.
// ---------------------------------------------------------------------------
#define GEMM_SMEM_BYTES 56832

#define GEMMH_LOAD(S, CH, APTR, BPTR, LDB)                                      \
    _Pragma("unroll")                                                           \
    for (int i = 0; i < 2; i++) {                                               \
        int id = tid + i * 256;                                                 \
        int r = id >> 2, c = id & 3;                                            \
        CP_ASYNC16(smem_u32(&As[S][r][c * 4]),                                  \
                   (APTR) + (size_t)(m0 + r) * 768 + (CH) * 32 + c * 8);        \
    }                                                                           \
    _Pragma("unroll")                                                           \
    for (int i = 0; i < 2; i++) {                                               \
        int id = tid + i * 256;                                                 \
        int r = id >> 5, c = id & 31;                                           \
        CP_ASYNC16(smem_u32(&Bs[S][r][c * 4]),                                  \
                   (BPTR) + (size_t)((CH) * 16 + r) * (LDB) + n0 + c * 4);      \
    }                                                                           \
    CP_COMMIT();

#define GEMMH_BODY(APTR, BPTR, LDB)                                             \
    extern __shared__ char smem_raw[];                                          \
    uint32_t (*As)[128][20] = (uint32_t (*)[128][20])smem_raw;                  \
    uint32_t (*Bs)[16][136] = (uint32_t (*)[16][136])(smem_raw + 3 * 128 * 20 * 4); \
    const int tid  = threadIdx.x;                                               \
    const int lane = tid & 31;                                                  \
    const int wid  = tid >> 5;                                                  \
    const int warp_m = wid & 1, warp_n = wid >> 1;                              \
    const int g = lane >> 2, tg = lane & 3;                                     \
    const int m0 = blockIdx.y * 128, n0 = blockIdx.x * 128;                     \
    float acc[4][4][4] = {};                                                    \
    GEMMH_LOAD(0, 0, APTR, BPTR, LDB)                                           \
    GEMMH_LOAD(1, 1, APTR, BPTR, LDB)                                           \
    int sidx = 0, pidx = 2;                                                     \
    for (int step = 0; step < 24; step++) {                                     \
        if (step < 23) { CP_WAIT(1); } else { CP_WAIT(0); }                     \
        __syncthreads();                                                        \
        if (step + 2 < 24) {                                                    \
            GEMMH_LOAD(pidx, step + 2, APTR, BPTR, LDB)                         \
        }                                                                       \
        const int s = sidx;                                                     \
        _Pragma("unroll")                                                       \
        for (int ks = 0; ks < 2; ks++) {                                        \
            const int kk = ks * 8;                                              \
            uint32_t afr[4][4], bfr[4][2];                                      \
            _Pragma("unroll")                                                   \
            for (int mt = 0; mt < 4; mt++) {                                    \
                const int rb = warp_m * 64 + mt * 16;                           \
                afr[mt][0] = As[s][rb + g][kk + tg];                            \
                afr[mt][1] = As[s][rb + g + 8][kk + tg];                        \
                afr[mt][2] = As[s][rb + g][kk + tg + 4];                        \
                afr[mt][3] = As[s][rb + g + 8][kk + tg + 4];                    \
            }                                                                   \
            _Pragma("unroll")                                                   \
            for (int nt = 0; nt < 4; nt++) {                                    \
                const int cb = warp_n * 32 + nt * 8;                            \
                bfr[nt][0] = Bs[s][kk + tg][cb + g];                            \
                bfr[nt][1] = Bs[s][kk + tg + 4][cb + g];                        \
            }                                                                   \
            _Pragma("unroll")                                                   \
            for (int mt = 0; mt < 4; mt++)                                      \
                _Pragma("unroll")                                               \
                for (int nt = 0; nt < 4; nt++)                                  \
                    mma_f16(acc[mt][nt], afr[mt], bfr[nt]);                     \
        }                                                                       \
        sidx = (sidx == 2) ? 0 : sidx + 1;                                      \
        pidx = (pidx == 2) ? 0 : pidx + 1;                                      \
    }

// ---------------------------------------------------------------------------
// Kernel 1: QKV GEMM (M=8192, N=2304, K=768) -> q/k/v half [B,H,T,64].
// ---------------------------------------------------------------------------
__global__ __launch_bounds__(256, 2) void gemm_qkv_h(const float* __restrict__ bias)
{
    GEMMH_BODY(g_x, g_wa_p, 2304)

#pragma unroll
    for (int mt = 0; mt < 4; mt++) {
#pragma unroll
        for (int nt = 0; nt < 4; nt++) {
            int n = n0 + warp_n * 32 + nt * 8 + 2 * tg;   // even
            int which = n / 768;
            int c = n - which * 768;
            int hh = c >> 6, d = c & 63;
            uint32_t* dstp = (uint32_t*)((which == 0) ? g_q : (which == 1) ? g_k : g_v);
            float b0 = bias[n], b1 = bias[n + 1];
            int row0 = m0 + warp_m * 64 + mt * 16 + g;
            int bb = row0 >> 10, t0 = row0 & 1023;
            size_t base = ((((size_t)bb * 12 + hh) << 10) + t0) * 32 + (d >> 1);
            dstp[base]          = packh2(acc[mt][nt][0] + b0, acc[mt][nt][1] + b1);
            dstp[base + 8 * 32] = packh2(acc[mt][nt][2] + b0, acc[mt][nt][3] + b1);
        }
    }
}

// ---------------------------------------------------------------------------
// Kernel 3: projection (M=8192, N=768, K=768): g_y(half) @ wp -> fp32 out.
// ---------------------------------------------------------------------------
__global__ __launch_bounds__(256, 2) void gemm_proj_h(
    const float* __restrict__ bias, float* __restrict__ out)
{
    GEMMH_BODY(g_y, g_wp_p, 768)

#pragma unroll
    for (int mt = 0; mt < 4; mt++) {
#pragma unroll
        for (int nt = 0; nt < 4; nt++) {
            int n = n0 + warp_n * 32 + nt * 8 + 2 * tg;
            float b0 = bias[n], b1 = bias[n + 1];
            int row0 = m0 + warp_m * 64 + mt * 16 + g;
            *(float2*)(out + (size_t)row0 * 768 + n) =
                make_float2(acc[mt][nt][0] + b0, acc[mt][nt][1] + b1);
            *(float2*)(out + (size_t)(row0 + 8) * 768 + n) =
                make_float2(acc[mt][nt][2] + b0, acc[mt][nt][3] + b1);
        }
    }
}

// ---------------------------------------------------------------------------
// Kernel 2 v3: causal flash attention, fp16 MMA / fp32 softmax.
// Q tile 128 rows (amortizes loads/softmax/barriers 2x), K/V tile 64.
// Grid (8, 96), 256 threads = 8 warps, warp m-split (16 rows x 64 cols each).
// Dynamic smem 73216B (2 CTAs/SM):
//   Sf  fp32 [128][68]     scores
//   Ks  uint32 [64][36]    K d-pairs
//   Vp  uint32 [32][72]    V t-pairs
//   Pp  uint32 [128][36]   P half t-pairs (also Q staging)
//   stats 3*128 floats
// ---------------------------------------------------------------------------
#define ATTN_SMEM_BYTES 73216
#define SF_OFF   0
#define KS_OFF   34816
#define VP_OFF   44032
#define PP_OFF   53248
#define ST_OFF   71680

__global__ __launch_bounds__(256, 2) void attn_h_kernel()
{
    extern __shared__ char smem_raw[];
    float    (*Sf)[68] = (float (*)[68])(smem_raw + SF_OFF);
    uint32_t (*Ks)[36] = (uint32_t (*)[36])(smem_raw + KS_OFF);
    uint32_t (*Vp)[72] = (uint32_t (*)[72])(smem_raw + VP_OFF);
    uint32_t (*Pp)[36] = (uint32_t (*)[36])(smem_raw + PP_OFF);
    float* s_m = (float*)(smem_raw + ST_OFF);
    float* s_l = s_m + 128;
    float* s_f = s_m + 256;

    const int tid = threadIdx.x;
    const int lane = tid & 31;
    const int wid = tid >> 5;
    const int g = lane >> 2, tg = lane & 3;
    const int qi = blockIdx.x, bh = blockIdx.y;
    const int q0 = qi * 128;
    const __half* qb = g_q + (size_t)bh * 65536;
    const __half* kb = g_k + (size_t)bh * 65536;
    const __half* vb = g_v + (size_t)bh * 65536;
    const int mr = wid * 16;

    // Stage Q (128 rows) into Pp, hoist this warp's A-fragments.
#pragma unroll
    for (int r = 0; r < 4; r++) {
        int id = tid + r * 256;
        int q = id >> 3, c = id & 7;
        *(uint4*)&Pp[q][c * 4] = *(const uint4*)(qb + (size_t)(q0 + q) * 64 + c * 8);
    }
    if (tid < 128) { s_m[tid] = -1e30f; s_l[tid] = 0.0f; }
    __syncthreads();

    uint32_t qfr[4][4];
#pragma unroll
    for (int ks = 0; ks < 4; ks++) {
        const int kk = ks * 8;
        qfr[ks][0] = Pp[mr + g][kk + tg];
        qfr[ks][1] = Pp[mr + g + 8][kk + tg];
        qfr[ks][2] = Pp[mr + g][kk + tg + 4];
        qfr[ks][3] = Pp[mr + g + 8][kk + tg + 4];
    }

    float acc_o[8][4] = {};

    const int ktiles = 2 * qi + 2;
    for (int kt = 0; kt < ktiles; kt++) {
        const int k0 = kt * 64;
        const bool dm = (k0 >= q0);   // only last two tiles need masking

        __syncthreads();   // qfr hoisted / prior tile reads done
        // load K tile (64 keys, d-pairs natural)
#pragma unroll
        for (int r = 0; r < 2; r++) {
            int id = tid + r * 256;
            int t = id >> 3, c = id & 7;
            *(uint4*)&Ks[t][c * 4] = *(const uint4*)(kb + (size_t)(k0 + t) * 64 + c * 8);
        }
        // load V tile, pack to t-pairs via byte_perm
#pragma unroll
        for (int j = 0; j < 4; j++) {
            int id = tid + j * 256;
            int i = id >> 5, d2 = id & 31;
            uint32_t r0 = *(const uint32_t*)(vb + (size_t)(k0 + 2 * i) * 64 + 2 * d2);
            uint32_t r1 = *(const uint32_t*)(vb + (size_t)(k0 + 2 * i + 1) * 64 + 2 * d2);
            Vp[i][2 * d2]     = __byte_perm(r0, r1, 0x5410);
            Vp[i][2 * d2 + 1] = __byte_perm(r0, r1, 0x7632);
        }
        __syncthreads();

        // ---- S = Q K^T  (warp: 16 rows x 64 k-cols) ----
        float acc_s[8][4] = {};
#pragma unroll
        for (int ks = 0; ks < 4; ks++) {
            const int kk = ks * 8;
#pragma unroll
            for (int nt = 0; nt < 8; nt++) {
                const int nc = nt * 8;
                uint32_t bfr[2];
                bfr[0] = Ks[nc + g][kk + tg];
                bfr[1] = Ks[nc + g][kk + tg + 4];
                mma_f16(acc_s[nt], qfr[ks], bfr);
            }
        }
        // mask + scale -> Sf (fp32)
#pragma unroll
        for (int nt = 0; nt < 8; nt++) {
            const int nc = nt * 8;
#pragma unroll
            for (int e = 0; e < 4; e++) {
                int row = mr + g + (e >> 1) * 8;
                int col = nc + 2 * tg + (e & 1);
                float v = acc_s[nt][e] * 0.125f;
                if (dm && (k0 + col) > (q0 + row)) v = -1e30f;
                Sf[row][col] = v;
            }
        }
        __syncthreads();

        // ---- online softmax: 2 threads per row, 32 cols each ----
        {
            const int row = tid >> 1, sub = tid & 1;
            float mold = s_m[row];
            float mt = mold;
            float vals[32];
#pragma unroll
            for (int j = 0; j < 32; j++) {
                vals[j] = Sf[row][sub * 32 + j];
                mt = fmaxf(mt, vals[j]);
            }
            mt = fmaxf(mt, __shfl_xor_sync(0xffffffffu, mt, 1));
            float ls = 0.0f;
#pragma unroll
            for (int j = 0; j < 32; j++) {
                vals[j] = __expf(vals[j] - mt);
                ls += vals[j];
            }
#pragma unroll
            for (int j2 = 0; j2 < 16; j2++)
                Pp[row][sub * 16 + j2] = packh2(vals[2 * j2], vals[2 * j2 + 1]);
            ls += __shfl_xor_sync(0xffffffffu, ls, 1);
            if (sub == 0) {
                float f = __expf(mold - mt);
                s_m[row] = mt;
                s_l[row] = s_l[row] * f + ls;
                s_f[row] = f;
            }
        }
        __syncthreads();

        // ---- rescale O, accumulate P @ V (warp: 16 rows x 64 d) ----
        float f0 = s_f[mr + g], f1 = s_f[mr + g + 8];
#pragma unroll
        for (int nt = 0; nt < 8; nt++) {
            acc_o[nt][0] *= f0; acc_o[nt][1] *= f0;
            acc_o[nt][2] *= f1; acc_o[nt][3] *= f1;
        }
#pragma unroll
        for (int ts = 0; ts < 4; ts++) {
            const int kk = ts * 8;
            uint32_t afr[4];
            afr[0] = Pp[mr + g][kk + tg];
            afr[1] = Pp[mr + g + 8][kk + tg];
            afr[2] = Pp[mr + g][kk + tg + 4];
            afr[3] = Pp[mr + g + 8][kk + tg + 4];
#pragma unroll
            for (int nt = 0; nt < 8; nt++) {
                const int nc = nt * 8;
                uint32_t bfr[2];
                bfr[0] = Vp[kk + tg][nc + g];
                bfr[1] = Vp[kk + tg + 4][nc + g];
                mma_f16(acc_o[nt], afr, bfr);
            }
        }
    }

    // ---- epilogue: normalize, write g_y (half) in [B,T,C] layout ----
    const int b = bh / 12, h = bh - b * 12;
    float inv0 = 1.0f / s_l[mr + g];
    float inv1 = 1.0f / s_l[mr + g + 8];
    const int t0 = q0 + mr + g, t1 = t0 + 8;
#pragma unroll
    for (int nt = 0; nt < 8; nt++) {
        int col = nt * 8 + 2 * tg;   // even
        uint32_t* d0 = (uint32_t*)(g_y + ((size_t)(b * 1024 + t0)) * 768 + h * 64 + col);
        uint32_t* d1 = (uint32_t*)(g_y + ((size_t)(b * 1024 + t1)) * 768 + h * 64 + col);
        *d0 = packh2(acc_o[nt][0] * inv0, acc_o[nt][1] * inv0);
        *d1 = packh2(acc_o[nt][2] * inv1, acc_o[nt][3] * inv1);
    }
}

// ---------------------------------------------------------------------------
extern "C" void kernel_launch(void* const* d_in, const int* in_sizes, int n_in,
                              void* d_out, int out_size)
{
    const float* x      = (const float*)d_in[0];
    const float* w_attn = (const float*)d_in[1];
    const float* b_attn = (const float*)d_in[2];
    const float* w_proj = (const float*)d_in[3];
    const float* b_proj = (const float*)d_in[4];
    float* out = (float*)d_out;

    static bool attr_set = false;
    if (!attr_set) {
        cudaFuncSetAttribute(gemm_qkv_h,
            cudaFuncAttributeMaxDynamicSharedMemorySize, GEMM_SMEM_BYTES);
        cudaFuncSetAttribute(gemm_proj_h,
            cudaFuncAttributeMaxDynamicSharedMemorySize, GEMM_SMEM_BYTES);
        cudaFuncSetAttribute(attn_h_kernel,
            cudaFuncAttributeMaxDynamicSharedMemorySize, ATTN_SMEM_BYTES);
        attr_set = true;
    }

    conv_x<<<6144, 256>>>(x);
    pack_w<<<3456, 256>>>(w_attn, 2304, 0);
    pack_w<<<1152, 256>>>(w_proj, 768, 1);
    gemm_qkv_h<<<dim3(18, 64), 256, GEMM_SMEM_BYTES>>>(b_attn);
    attn_h_kernel<<<dim3(8, 96), 256, ATTN_SMEM_BYTES>>>();
    gemm_proj_h<<<dim3(6, 64), 256, GEMM_SMEM_BYTES>>>(b_proj, out);
}

// round 16
// speedup vs baseline: 1.1706x; 1.1706x over previous
#include <cuda_runtime.h>
#include <cuda_fp16.h>
#include <cstdint>

// Problem constants: B=8, T=1024, C=768, H=12, HD=64
// All scratch in fp16 (half).
__device__ __half g_q[6291456];          // [96][1024][64]
__device__ __half g_k[6291456];
__device__ __half g_v[6291456];
__device__ __half g_y[6291456];          // [8192][768]
__device__ __half g_x[6291456];          // [8192][768]
__device__ uint32_t g_wa_p[884736];      // packed w_attn [k2=384][2304]
__device__ uint32_t g_wp_p[294912];      // packed w_proj [k2=384][768]

// ---------------------------------------------------------------------------
// helpers
// ---------------------------------------------------------------------------
__device__ __forceinline__ void mma_f16(float* c, const uint32_t* a, const uint32_t* b) {
    asm volatile(
        "mma.sync.aligned.m16n8k16.row.col.f32.f16.f16.f32 "
        "{%0,%1,%2,%3},{%4,%5,%6,%7},{%8,%9},{%0,%1,%2,%3};"
        : "+f"(c[0]), "+f"(c[1]), "+f"(c[2]), "+f"(c[3])
        : "r"(a[0]), "r"(a[1]), "r"(a[2]), "r"(a[3]), "r"(b[0]), "r"(b[1]));
}
__device__ __forceinline__ uint32_t smem_u32(const void* p) {
    return (uint32_t)__cvta_generic_to_shared(p);
}
__device__ __forceinline__ uint32_t packh2(float a, float b) {
    __half2 h = __floats2half2_rn(a, b);
    return *(uint32_t*)&h;
}
#define CP_ASYNC16(dst, src) \
    asm volatile("cp.async.cg.shared.global [%0], [%1], 16;\n" :: "r"(dst), "l"(src))
#define CP_COMMIT() asm volatile("cp.async.commit_group;\n")
#define CP_WAIT(N)  asm volatile("cp.async.wait_group %0;\n" :: "n"(N))

// ---------------------------------------------------------------------------
// Kernel 0a: x (float) -> g_x (half).
// ---------------------------------------------------------------------------
__global__ __launch_bounds__(256) void conv_x(const float* __restrict__ x)
{
    long i = (long)blockIdx.x * 256 + threadIdx.x;   // 1572864 float4s
    float4 v = ((const float4*)x)[i];
    uint2 o;
    o.x = packh2(v.x, v.y);
    o.y = packh2(v.z, v.w);
    ((uint2*)g_x)[i] = o;
}

// ---------------------------------------------------------------------------
// Kernel 0b: pack weights: dst[k2*N + n] = half2(w[2k2][n], w[2k2+1][n]).
// Destination selected IN-KERNEL (device symbols must not cross host ABI).
// ---------------------------------------------------------------------------
__global__ __launch_bounds__(256) void pack_w(
    const float* __restrict__ src, int N, int which)
{
    uint32_t* dst = which ? g_wp_p : g_wa_p;
    int idx = blockIdx.x * 256 + threadIdx.x;
    int k2 = idx / N, n = idx - k2 * N;
    float a = src[(size_t)(2 * k2) * N + n];
    float b = src[(size_t)(2 * k2 + 1) * N + n];
    dst[idx] = packh2(a, b);
}

// ---------------------------------------------------------------------------
// FP16 GEMM core (R13 proven, verbatim): block tile 128x128, 8 warps (2m x 4n),
// warp tile 64x32, K-step 32 halfs, 24 steps, 3-stage cp.async, 1 sync/step.
// ---------------------------------------------------------------------------
#define GEMM_SMEM_BYTES 56832

#define GEMMH_LOAD(S, CH, APTR, BPTR, LDB)                                      \
    _Pragma("unroll")                                                           \
    for (int i = 0; i < 2; i++) {                                               \
        int id = tid + i * 256;                                                 \
        int r = id >> 2, c = id & 3;                                            \
        CP_ASYNC16(smem_u32(&As[S][r][c * 4]),                                  \
                   (APTR) + (size_t)(m0 + r) * 768 + (CH) * 32 + c * 8);        \
    }                                                                           \
    _Pragma("unroll")                                                           \
    for (int i = 0; i < 2; i++) {                                               \
        int id = tid + i * 256;                                                 \
        int r = id >> 5, c = id & 31;                                           \
        CP_ASYNC16(smem_u32(&Bs[S][r][c * 4]),                                  \
                   (BPTR) + (size_t)((CH) * 16 + r) * (LDB) + n0 + c * 4);      \
    }                                                                           \
    CP_COMMIT();

#define GEMMH_BODY(APTR, BPTR, LDB)                                             \
    extern __shared__ char smem_raw[];                                          \
    uint32_t (*As)[128][20] = (uint32_t (*)[128][20])smem_raw;                  \
    uint32_t (*Bs)[16][136] = (uint32_t (*)[16][136])(smem_raw + 3 * 128 * 20 * 4); \
    const int tid  = threadIdx.x;                                               \
    const int lane = tid & 31;                                                  \
    const int wid  = tid >> 5;                                                  \
    const int warp_m = wid & 1, warp_n = wid >> 1;                              \
    const int g = lane >> 2, tg = lane & 3;                                     \
    const int m0 = blockIdx.y * 128, n0 = blockIdx.x * 128;                     \
    float acc[4][4][4] = {};                                                    \
    GEMMH_LOAD(0, 0, APTR, BPTR, LDB)                                           \
    GEMMH_LOAD(1, 1, APTR, BPTR, LDB)                                           \
    int sidx = 0, pidx = 2;                                                     \
    for (int step = 0; step < 24; step++) {                                     \
        if (step < 23) { CP_WAIT(1); } else { CP_WAIT(0); }                     \
        __syncthreads();                                                        \
        if (step + 2 < 24) {                                                    \
            GEMMH_LOAD(pidx, step + 2, APTR, BPTR, LDB)                         \
        }                                                                       \
        const int s = sidx;                                                     \
        _Pragma("unroll")                                                       \
        for (int ks = 0; ks < 2; ks++) {                                        \
            const int kk = ks * 8;                                              \
            uint32_t afr[4][4], bfr[4][2];                                      \
            _Pragma("unroll")                                                   \
            for (int mt = 0; mt < 4; mt++) {                                    \
                const int rb = warp_m * 64 + mt * 16;                           \
                afr[mt][0] = As[s][rb + g][kk + tg];                            \
                afr[mt][1] = As[s][rb + g + 8][kk + tg];                        \
                afr[mt][2] = As[s][rb + g][kk + tg + 4];                        \
                afr[mt][3] = As[s][rb + g + 8][kk + tg + 4];                    \
            }                                                                   \
            _Pragma("unroll")                                                   \
            for (int nt = 0; nt < 4; nt++) {                                    \
                const int cb = warp_n * 32 + nt * 8;                            \
                bfr[nt][0] = Bs[s][kk + tg][cb + g];                            \
                bfr[nt][1] = Bs[s][kk + tg + 4][cb + g];                        \
            }                                                                   \
            _Pragma("unroll")                                                   \
            for (int mt = 0; mt < 4; mt++)                                      \
                _Pragma("unroll")                                               \
                for (int nt = 0; nt < 4; nt++)                                  \
                    mma_f16(acc[mt][nt], afr[mt], bfr[nt]);                     \
        }                                                                       \
        sidx = (sidx == 2) ? 0 : sidx + 1;                                      \
        pidx = (pidx == 2) ? 0 : pidx + 1;                                      \
    }

// ---------------------------------------------------------------------------
// Kernel 1: QKV GEMM (M=8192, N=2304, K=768) -> q/k/v half [B,H,T,64].
// ---------------------------------------------------------------------------
__global__ __launch_bounds__(256, 2) void gemm_qkv_h(const float* __restrict__ bias)
{
    GEMMH_BODY(g_x, g_wa_p, 2304)

#pragma unroll
    for (int mt = 0; mt < 4; mt++) {
#pragma unroll
        for (int nt = 0; nt < 4; nt++) {
            int n = n0 + warp_n * 32 + nt * 8 + 2 * tg;   // even
            int which = n / 768;
            int c = n - which * 768;
            int hh = c >> 6, d = c & 63;
            uint32_t* dstp = (uint32_t*)((which == 0) ? g_q : (which == 1) ? g_k : g_v);
            float b0 = bias[n], b1 = bias[n + 1];
            int row0 = m0 + warp_m * 64 + mt * 16 + g;
            int bb = row0 >> 10, t0 = row0 & 1023;
            size_t base = ((((size_t)bb * 12 + hh) << 10) + t0) * 32 + (d >> 1);
            dstp[base]          = packh2(acc[mt][nt][0] + b0, acc[mt][nt][1] + b1);
            dstp[base + 8 * 32] = packh2(acc[mt][nt][2] + b0, acc[mt][nt][3] + b1);
        }
    }
}

// ---------------------------------------------------------------------------
// Kernel 3: projection (M=8192, N=768, K=768): g_y(half) @ wp -> fp32 out.
// ---------------------------------------------------------------------------
__global__ __launch_bounds__(256, 2) void gemm_proj_h(
    const float* __restrict__ bias, float* __restrict__ out)
{
    GEMMH_BODY(g_y, g_wp_p, 768)

#pragma unroll
    for (int mt = 0; mt < 4; mt++) {
#pragma unroll
        for (int nt = 0; nt < 4; nt++) {
            int n = n0 + warp_n * 32 + nt * 8 + 2 * tg;
            float b0 = bias[n], b1 = bias[n + 1];
            int row0 = m0 + warp_m * 64 + mt * 16 + g;
            *(float2*)(out + (size_t)row0 * 768 + n) =
                make_float2(acc[mt][nt][0] + b0, acc[mt][nt][1] + b1);
            *(float2*)(out + (size_t)(row0 + 8) * 768 + n) =
                make_float2(acc[mt][nt][2] + b0, acc[mt][nt][3] + b1);
        }
    }
}

// ---------------------------------------------------------------------------
// Kernel 2 v4: causal flash attention with FULLY IN-REGISTER softmax.
// Q tile 128 rows, K/V tile 64.  Grid (8, 96), 256 threads = 8 warps,
// warp m-split: warp w owns rows w*16..w*16+15 across ALL 64 keys.
// The S C-fragment layout IS the P A-fragment layout (repack via packh2) --
// no smem round trip for scores, no smem stats, 2 barriers/tile.
// Static smem 18432B: SM[128][36]; Q staging aliases K(rows 0-63)+Vp(64-127).
// ---------------------------------------------------------------------------
__global__ __launch_bounds__(256, 2) void attn_h_kernel()
{
    __shared__ uint32_t SM[128][36];
    uint32_t (*Ks)[36] = SM;                               // K tile, 64 rows
    uint32_t (*Vp)[72] = (uint32_t (*)[72])(&SM[64][0]);   // V packed 32x72

    const int tid = threadIdx.x;
    const int lane = tid & 31;
    const int wid = tid >> 5;
    const int g = lane >> 2, tg = lane & 3;
    const int qi = blockIdx.x, bh = blockIdx.y;
    const int q0 = qi * 128;
    const __half* qb = g_q + (size_t)bh * 65536;
    const __half* kb = g_k + (size_t)bh * 65536;
    const __half* vb = g_v + (size_t)bh * 65536;
    const int mr = wid * 16;

    // Stage Q (128 rows) into SM, hoist this warp's A-fragments.
#pragma unroll
    for (int r = 0; r < 4; r++) {
        int id = tid + r * 256;
        int q = id >> 3, c = id & 7;
        *(uint4*)&SM[q][c * 4] = *(const uint4*)(qb + (size_t)(q0 + q) * 64 + c * 8);
    }
    __syncthreads();

    uint32_t qfr[4][4];
#pragma unroll
    for (int ks = 0; ks < 4; ks++) {
        const int kk = ks * 8;
        qfr[ks][0] = SM[mr + g][kk + tg];
        qfr[ks][1] = SM[mr + g + 8][kk + tg];
        qfr[ks][2] = SM[mr + g][kk + tg + 4];
        qfr[ks][3] = SM[mr + g + 8][kk + tg + 4];
    }

    // Per-thread row stats (rows mr+g and mr+g+8; identical across each quad).
    float m0 = -1e30f, m1 = -1e30f, l0 = 0.0f, l1 = 0.0f;
    float acc_o[8][4] = {};

    const int row0g = q0 + mr + g, row1g = row0g + 8;
    const int ktiles = 2 * qi + 2;
    for (int kt = 0; kt < ktiles; kt++) {
        const int k0 = kt * 64;

        __syncthreads();   // prior tile's Ks/Vp reads done (Q reads on iter 0)
        // load K tile (64 keys, d-pairs natural)
#pragma unroll
        for (int r = 0; r < 2; r++) {
            int id = tid + r * 256;
            int t = id >> 3, c = id & 7;
            *(uint4*)&Ks[t][c * 4] = *(const uint4*)(kb + (size_t)(k0 + t) * 64 + c * 8);
        }
        // load V tile, pack to key-pairs via byte_perm
#pragma unroll
        for (int j = 0; j < 4; j++) {
            int id = tid + j * 256;
            int i = id >> 5, d2 = id & 31;
            uint32_t r0 = *(const uint32_t*)(vb + (size_t)(k0 + 2 * i) * 64 + 2 * d2);
            uint32_t r1 = *(const uint32_t*)(vb + (size_t)(k0 + 2 * i + 1) * 64 + 2 * d2);
            Vp[i][2 * d2]     = __byte_perm(r0, r1, 0x5410);
            Vp[i][2 * d2 + 1] = __byte_perm(r0, r1, 0x7632);
        }
        __syncthreads();

        // Warps whose 16 rows are entirely above the diagonal: nothing to do.
        if (k0 > q0 + mr + 15) continue;

        // ---- S = Q K^T  (warp: 16 rows x 64 keys) ----
        float s[8][4] = {};
#pragma unroll
        for (int ks = 0; ks < 4; ks++) {
            const int kk = ks * 8;
#pragma unroll
            for (int nt = 0; nt < 8; nt++) {
                const int nc = nt * 8;
                uint32_t bfr[2];
                bfr[0] = Ks[nc + g][kk + tg];
                bfr[1] = Ks[nc + g][kk + tg + 4];
                mma_f16(s[nt], qfr[ks], bfr);
            }
        }

        // ---- scale + causal mask (registers) ----
        const bool dm = (kt >= 2 * qi);
#pragma unroll
        for (int nt = 0; nt < 8; nt++) {
            const int c0 = k0 + nt * 8 + 2 * tg;
            s[nt][0] *= 0.125f; s[nt][1] *= 0.125f;
            s[nt][2] *= 0.125f; s[nt][3] *= 0.125f;
            if (dm) {
                if (c0 > row0g)     s[nt][0] = -1e30f;
                if (c0 + 1 > row0g) s[nt][1] = -1e30f;
                if (c0 > row1g)     s[nt][2] = -1e30f;
                if (c0 + 1 > row1g) s[nt][3] = -1e30f;
            }
        }

        // ---- in-register online softmax (quad shuffles) ----
        float mt0 = -1e30f, mt1 = -1e30f;
#pragma unroll
        for (int nt = 0; nt < 8; nt++) {
            mt0 = fmaxf(mt0, fmaxf(s[nt][0], s[nt][1]));
            mt1 = fmaxf(mt1, fmaxf(s[nt][2], s[nt][3]));
        }
        mt0 = fmaxf(mt0, __shfl_xor_sync(0xffffffffu, mt0, 1));
        mt0 = fmaxf(mt0, __shfl_xor_sync(0xffffffffu, mt0, 2));
        mt1 = fmaxf(mt1, __shfl_xor_sync(0xffffffffu, mt1, 1));
        mt1 = fmaxf(mt1, __shfl_xor_sync(0xffffffffu, mt1, 2));
        float mn0 = fmaxf(m0, mt0), mn1 = fmaxf(m1, mt1);
        float f0 = __expf(m0 - mn0), f1 = __expf(m1 - mn1);
        float ls0 = 0.0f, ls1 = 0.0f;
#pragma unroll
        for (int nt = 0; nt < 8; nt++) {
            s[nt][0] = __expf(s[nt][0] - mn0); ls0 += s[nt][0];
            s[nt][1] = __expf(s[nt][1] - mn0); ls0 += s[nt][1];
            s[nt][2] = __expf(s[nt][2] - mn1); ls1 += s[nt][2];
            s[nt][3] = __expf(s[nt][3] - mn1); ls1 += s[nt][3];
        }
        ls0 += __shfl_xor_sync(0xffffffffu, ls0, 1);
        ls0 += __shfl_xor_sync(0xffffffffu, ls0, 2);
        ls1 += __shfl_xor_sync(0xffffffffu, ls1, 1);
        ls1 += __shfl_xor_sync(0xffffffffu, ls1, 2);
        m0 = mn0; m1 = mn1;
        l0 = l0 * f0 + ls0;
        l1 = l1 * f1 + ls1;

        // ---- rescale O, pack P frags in-register, P @ V ----
#pragma unroll
        for (int nt = 0; nt < 8; nt++) {
            acc_o[nt][0] *= f0; acc_o[nt][1] *= f0;
            acc_o[nt][2] *= f1; acc_o[nt][3] *= f1;
        }
#pragma unroll
        for (int ts = 0; ts < 4; ts++) {
            uint32_t pfr[4];
            pfr[0] = packh2(s[2 * ts][0], s[2 * ts][1]);
            pfr[1] = packh2(s[2 * ts][2], s[2 * ts][3]);
            pfr[2] = packh2(s[2 * ts + 1][0], s[2 * ts + 1][1]);
            pfr[3] = packh2(s[2 * ts + 1][2], s[2 * ts + 1][3]);
#pragma unroll
            for (int nt = 0; nt < 8; nt++) {
                const int nc = nt * 8;
                uint32_t bfr[2];
                bfr[0] = Vp[ts * 8 + tg][nc + g];
                bfr[1] = Vp[ts * 8 + tg + 4][nc + g];
                mma_f16(acc_o[nt], pfr, bfr);
            }
        }
    }

    // ---- epilogue: normalize, write g_y (half) in [B,T,C] layout ----
    const int b = bh / 12, h = bh - b * 12;
    float inv0 = 1.0f / l0;
    float inv1 = 1.0f / l1;
    const int t0 = q0 + mr + g, t1 = t0 + 8;
#pragma unroll
    for (int nt = 0; nt < 8; nt++) {
        int col = nt * 8 + 2 * tg;   // even
        uint32_t* d0 = (uint32_t*)(g_y + ((size_t)(b * 1024 + t0)) * 768 + h * 64 + col);
        uint32_t* d1 = (uint32_t*)(g_y + ((size_t)(b * 1024 + t1)) * 768 + h * 64 + col);
        *d0 = packh2(acc_o[nt][0] * inv0, acc_o[nt][1] * inv0);
        *d1 = packh2(acc_o[nt][2] * inv1, acc_o[nt][3] * inv1);
    }
}

// ---------------------------------------------------------------------------
extern "C" void kernel_launch(void* const* d_in, const int* in_sizes, int n_in,
                              void* d_out, int out_size)
{
    const float* x      = (const float*)d_in[0];
    const float* w_attn = (const float*)d_in[1];
    const float* b_attn = (const float*)d_in[2];
    const float* w_proj = (const float*)d_in[3];
    const float* b_proj = (const float*)d_in[4];
    float* out = (float*)d_out;

    static bool attr_set = false;
    if (!attr_set) {
        cudaFuncSetAttribute(gemm_qkv_h,
            cudaFuncAttributeMaxDynamicSharedMemorySize, GEMM_SMEM_BYTES);
        cudaFuncSetAttribute(gemm_proj_h,
            cudaFuncAttributeMaxDynamicSharedMemorySize, GEMM_SMEM_BYTES);
        attr_set = true;
    }

    conv_x<<<6144, 256>>>(x);
    pack_w<<<3456, 256>>>(w_attn, 2304, 0);
    pack_w<<<1152, 256>>>(w_proj, 768, 1);
    gemm_qkv_h<<<dim3(18, 64), 256, GEMM_SMEM_BYTES>>>(b_attn);
    attn_h_kernel<<<dim3(8, 96), 256>>>();
    gemm_proj_h<<<dim3(6, 64), 256, GEMM_SMEM_BYTES>>>(b_proj, out);
}

// round 17
// speedup vs baseline: 1.1987x; 1.0240x over previous
#include <cuda_runtime.h>
#include <cuda_fp16.h>
#include <cstdint>

// Problem constants: B=8, T=1024, C=768, H=12, HD=64
// All scratch in fp16 (half).
__device__ __half g_q[6291456];          // [96][1024][64]
__device__ __half g_k[6291456];
__device__ __half g_v[6291456];
__device__ __half g_y[6291456];          // [8192][768]
__device__ __half g_x[6291456];          // [8192][768]
__device__ uint32_t g_wa_p[884736];      // packed w_attn [k2=384][2304]
__device__ uint32_t g_wp_p[294912];      // packed w_proj [k2=384][768]

// ---------------------------------------------------------------------------
// helpers
// ---------------------------------------------------------------------------
__device__ __forceinline__ void mma_f16(float* c, const uint32_t* a, const uint32_t* b) {
    asm volatile(
        "mma.sync.aligned.m16n8k16.row.col.f32.f16.f16.f32 "
        "{%0,%1,%2,%3},{%4,%5,%6,%7},{%8,%9},{%0,%1,%2,%3};"
        : "+f"(c[0]), "+f"(c[1]), "+f"(c[2]), "+f"(c[3])
        : "r"(a[0]), "r"(a[1]), "r"(a[2]), "r"(a[3]), "r"(b[0]), "r"(b[1]));
}
__device__ __forceinline__ uint32_t smem_u32(const void* p) {
    return (uint32_t)__cvta_generic_to_shared(p);
}
__device__ __forceinline__ uint32_t packh2(float a, float b) {
    __half2 h = __floats2half2_rn(a, b);
    return *(uint32_t*)&h;
}
#define CP_ASYNC16(dst, src) \
    asm volatile("cp.async.cg.shared.global [%0], [%1], 16;\n" :: "r"(dst), "l"(src))
#define CP_COMMIT() asm volatile("cp.async.commit_group;\n")
#define CP_WAIT(N)  asm volatile("cp.async.wait_group %0;\n" :: "n"(N))

// ---------------------------------------------------------------------------
// Kernel 0 (fused): conv x -> half  |  pack w_attn  |  pack w_proj.
// Block ranges: [0,6144) conv_x, [6144,9600) wa, [9600,10752) wp.
// Device-global destinations selected in-kernel.
// ---------------------------------------------------------------------------
__global__ __launch_bounds__(256) void prep_kernel(
    const float* __restrict__ x, const float* __restrict__ wa,
    const float* __restrict__ wp)
{
    int blk = blockIdx.x;
    if (blk < 6144) {
        long i = (long)blk * 256 + threadIdx.x;   // 1572864 float4s
        float4 v = ((const float4*)x)[i];
        uint2 o;
        o.x = packh2(v.x, v.y);
        o.y = packh2(v.z, v.w);
        ((uint2*)g_x)[i] = o;
    } else if (blk < 9600) {
        int idx = (blk - 6144) * 256 + threadIdx.x;   // 884736
        int k2 = idx / 2304, n = idx - k2 * 2304;
        g_wa_p[idx] = packh2(wa[(size_t)(2 * k2) * 2304 + n],
                             wa[(size_t)(2 * k2 + 1) * 2304 + n]);
    } else {
        int idx = (blk - 9600) * 256 + threadIdx.x;   // 294912
        int k2 = idx / 768, n = idx - k2 * 768;
        g_wp_p[idx] = packh2(wp[(size_t)(2 * k2) * 768 + n],
                             wp[(size_t)(2 * k2 + 1) * 768 + n]);
    }
}

// ---------------------------------------------------------------------------
// FP16 GEMM core (R13 proven, verbatim): block tile 128x128, 8 warps (2m x 4n),
// warp tile 64x32, K-step 32 halfs, 24 steps, 3-stage cp.async, 1 sync/step.
// ---------------------------------------------------------------------------
#define GEMM_SMEM_BYTES 56832

#define GEMMH_LOAD(S, CH, APTR, BPTR, LDB)                                      \
    _Pragma("unroll")                                                           \
    for (int i = 0; i < 2; i++) {                                               \
        int id = tid + i * 256;                                                 \
        int r = id >> 2, c = id & 3;                                            \
        CP_ASYNC16(smem_u32(&As[S][r][c * 4]),                                  \
                   (APTR) + (size_t)(m0 + r) * 768 + (CH) * 32 + c * 8);        \
    }                                                                           \
    _Pragma("unroll")                                                           \
    for (int i = 0; i < 2; i++) {                                               \
        int id = tid + i * 256;                                                 \
        int r = id >> 5, c = id & 31;                                           \
        CP_ASYNC16(smem_u32(&Bs[S][r][c * 4]),                                  \
                   (BPTR) + (size_t)((CH) * 16 + r) * (LDB) + n0 + c * 4);      \
    }                                                                           \
    CP_COMMIT();

#define GEMMH_BODY(APTR, BPTR, LDB)                                             \
    extern __shared__ char smem_raw[];                                          \
    uint32_t (*As)[128][20] = (uint32_t (*)[128][20])smem_raw;                  \
    uint32_t (*Bs)[16][136] = (uint32_t (*)[16][136])(smem_raw + 3 * 128 * 20 * 4); \
    const int tid  = threadIdx.x;                                               \
    const int lane = tid & 31;                                                  \
    const int wid  = tid >> 5;                                                  \
    const int warp_m = wid & 1, warp_n = wid >> 1;                              \
    const int g = lane >> 2, tg = lane & 3;                                     \
    const int m0 = blockIdx.y * 128, n0 = blockIdx.x * 128;                     \
    float acc[4][4][4] = {};                                                    \
    GEMMH_LOAD(0, 0, APTR, BPTR, LDB)                                           \
    GEMMH_LOAD(1, 1, APTR, BPTR, LDB)                                           \
    int sidx = 0, pidx = 2;                                                     \
    for (int step = 0; step < 24; step++) {                                     \
        if (step < 23) { CP_WAIT(1); } else { CP_WAIT(0); }                     \
        __syncthreads();                                                        \
        if (step + 2 < 24) {                                                    \
            GEMMH_LOAD(pidx, step + 2, APTR, BPTR, LDB)                         \
        }                                                                       \
        const int s = sidx;                                                     \
        _Pragma("unroll")                                                       \
        for (int ks = 0; ks < 2; ks++) {                                        \
            const int kk = ks * 8;                                              \
            uint32_t afr[4][4], bfr[4][2];                                      \
            _Pragma("unroll")                                                   \
            for (int mt = 0; mt < 4; mt++) {                                    \
                const int rb = warp_m * 64 + mt * 16;                           \
                afr[mt][0] = As[s][rb + g][kk + tg];                            \
                afr[mt][1] = As[s][rb + g + 8][kk + tg];                        \
                afr[mt][2] = As[s][rb + g][kk + tg + 4];                        \
                afr[mt][3] = As[s][rb + g + 8][kk + tg + 4];                    \
            }                                                                   \
            _Pragma("unroll")                                                   \
            for (int nt = 0; nt < 4; nt++) {                                    \
                const int cb = warp_n * 32 + nt * 8;                            \
                bfr[nt][0] = Bs[s][kk + tg][cb + g];                            \
                bfr[nt][1] = Bs[s][kk + tg + 4][cb + g];                        \
            }                                                                   \
            _Pragma("unroll")                                                   \
            for (int mt = 0; mt < 4; mt++)                                      \
                _Pragma("unroll")                                               \
                for (int nt = 0; nt < 4; nt++)                                  \
                    mma_f16(acc[mt][nt], afr[mt], bfr[nt]);                     \
        }                                                                       \
        sidx = (sidx == 2) ? 0 : sidx + 1;                                      \
        pidx = (pidx == 2) ? 0 : pidx + 1;                                      \
    }

// ---------------------------------------------------------------------------
// Kernel 1: QKV GEMM (M=8192, N=2304, K=768) -> q/k/v half [B,H,T,64].
// ---------------------------------------------------------------------------
__global__ __launch_bounds__(256, 2) void gemm_qkv_h(const float* __restrict__ bias)
{
    GEMMH_BODY(g_x, g_wa_p, 2304)

#pragma unroll
    for (int mt = 0; mt < 4; mt++) {
#pragma unroll
        for (int nt = 0; nt < 4; nt++) {
            int n = n0 + warp_n * 32 + nt * 8 + 2 * tg;   // even
            int which = n / 768;
            int c = n - which * 768;
            int hh = c >> 6, d = c & 63;
            uint32_t* dstp = (uint32_t*)((which == 0) ? g_q : (which == 1) ? g_k : g_v);
            float b0 = bias[n], b1 = bias[n + 1];
            int row0 = m0 + warp_m * 64 + mt * 16 + g;
            int bb = row0 >> 10, t0 = row0 & 1023;
            size_t base = ((((size_t)bb * 12 + hh) << 10) + t0) * 32 + (d >> 1);
            dstp[base]          = packh2(acc[mt][nt][0] + b0, acc[mt][nt][1] + b1);
            dstp[base + 8 * 32] = packh2(acc[mt][nt][2] + b0, acc[mt][nt][3] + b1);
        }
    }
}

// ---------------------------------------------------------------------------
// Kernel 3: projection (M=8192, N=768, K=768): g_y(half) @ wp -> fp32 out.
// ---------------------------------------------------------------------------
__global__ __launch_bounds__(256, 2) void gemm_proj_h(
    const float* __restrict__ bias, float* __restrict__ out)
{
    GEMMH_BODY(g_y, g_wp_p, 768)

#pragma unroll
    for (int mt = 0; mt < 4; mt++) {
#pragma unroll
        for (int nt = 0; nt < 4; nt++) {
            int n = n0 + warp_n * 32 + nt * 8 + 2 * tg;
            float b0 = bias[n], b1 = bias[n + 1];
            int row0 = m0 + warp_m * 64 + mt * 16 + g;
            *(float2*)(out + (size_t)row0 * 768 + n) =
                make_float2(acc[mt][nt][0] + b0, acc[mt][nt][1] + b1);
            *(float2*)(out + (size_t)(row0 + 8) * 768 + n) =
                make_float2(acc[mt][nt][2] + b0, acc[mt][nt][3] + b1);
        }
    }
}

// ---------------------------------------------------------------------------
// Kernel 2 v5: causal flash attention, in-register softmax + REGISTER-STAGED
// K/V PREFETCH: next tile's LDGs issue right after this tile's STS barrier,
// overlapping global latency with compute.  Q tile 128, K/V tile 64.
// Grid (8, 96), 256 threads = 8 warps (m-split 16 rows each).
// Static smem 18432B: SM[128][36]; Q staging aliases K(0-63)+Vp(64-127).
// ---------------------------------------------------------------------------
__global__ __launch_bounds__(256, 2) void attn_h_kernel()
{
    __shared__ uint32_t SM[128][36];
    uint32_t (*Ks)[36] = SM;                               // K tile, 64 rows
    uint32_t (*Vp)[72] = (uint32_t (*)[72])(&SM[64][0]);   // V packed 32x72

    const int tid = threadIdx.x;
    const int lane = tid & 31;
    const int wid = tid >> 5;
    const int g = lane >> 2, tg = lane & 3;
    const int qi = blockIdx.x, bh = blockIdx.y;
    const int q0 = qi * 128;
    const __half* qb = g_q + (size_t)bh * 65536;
    const __half* kb = g_k + (size_t)bh * 65536;
    const __half* vb = g_v + (size_t)bh * 65536;
    const int mr = wid * 16;

    // Per-thread load coordinates (fixed across tiles)
    const int k_row0 = tid >> 3,        k_c = (tid & 7) * 8;   // K: rows tid>>3, +32
    const int v_i0   = tid >> 5,        v_d2 = (tid & 31) * 2; // V: pair rows tid>>5, +8,+16,+24

    // Stage Q (128 rows) into SM, hoist this warp's A-fragments.
#pragma unroll
    for (int r = 0; r < 4; r++) {
        int id = tid + r * 256;
        int q = id >> 3, c = id & 7;
        *(uint4*)&SM[q][c * 4] = *(const uint4*)(qb + (size_t)(q0 + q) * 64 + c * 8);
    }
    __syncthreads();

    uint32_t qfr[4][4];
#pragma unroll
    for (int ks = 0; ks < 4; ks++) {
        const int kk = ks * 8;
        qfr[ks][0] = SM[mr + g][kk + tg];
        qfr[ks][1] = SM[mr + g + 8][kk + tg];
        qfr[ks][2] = SM[mr + g][kk + tg + 4];
        qfr[ks][3] = SM[mr + g + 8][kk + tg + 4];
    }

    float m0 = -1e30f, m1 = -1e30f, l0 = 0.0f, l1 = 0.0f;
    float acc_o[8][4] = {};

    const int row0g = q0 + mr + g, row1g = row0g + 8;
    const int ktiles = 2 * qi + 2;

    // ---- prefetch tile 0 into registers ----
    uint4 kreg[2];
    uint32_t vr0[4], vr1[4];
#pragma unroll
    for (int r = 0; r < 2; r++)
        kreg[r] = *(const uint4*)(kb + (size_t)(k_row0 + r * 32) * 64 + k_c);
#pragma unroll
    for (int j = 0; j < 4; j++) {
        int i = v_i0 + j * 8;
        vr0[j] = *(const uint32_t*)(vb + (size_t)(2 * i) * 64 + v_d2);
        vr1[j] = *(const uint32_t*)(vb + (size_t)(2 * i + 1) * 64 + v_d2);
    }

    for (int kt = 0; kt < ktiles; kt++) {
        const int k0 = kt * 64;

        __syncthreads();   // prior tile's Ks/Vp reads done (Q reads on iter 0)
        // STS staged K and packed V
#pragma unroll
        for (int r = 0; r < 2; r++)
            *(uint4*)&Ks[k_row0 + r * 32][(k_c >> 1)] = kreg[r];
#pragma unroll
        for (int j = 0; j < 4; j++) {
            int i = v_i0 + j * 8;
            Vp[i][v_d2]     = __byte_perm(vr0[j], vr1[j], 0x5410);
            Vp[i][v_d2 + 1] = __byte_perm(vr0[j], vr1[j], 0x7632);
        }
        __syncthreads();

        // ---- issue next tile's LDGs (latency overlaps compute below) ----
        if (kt + 1 < ktiles) {
            const int k0n = k0 + 64;
#pragma unroll
            for (int r = 0; r < 2; r++)
                kreg[r] = *(const uint4*)(kb + (size_t)(k0n + k_row0 + r * 32) * 64 + k_c);
#pragma unroll
            for (int j = 0; j < 4; j++) {
                int i = v_i0 + j * 8;
                vr0[j] = *(const uint32_t*)(vb + (size_t)(k0n + 2 * i) * 64 + v_d2);
                vr1[j] = *(const uint32_t*)(vb + (size_t)(k0n + 2 * i + 1) * 64 + v_d2);
            }
        }

        // Warps whose 16 rows are entirely above the diagonal: skip compute.
        if (k0 > q0 + mr + 15) continue;

        // ---- S = Q K^T  (warp: 16 rows x 64 keys) ----
        float s[8][4] = {};
#pragma unroll
        for (int ks = 0; ks < 4; ks++) {
            const int kk = ks * 8;
#pragma unroll
            for (int nt = 0; nt < 8; nt++) {
                const int nc = nt * 8;
                uint32_t bfr[2];
                bfr[0] = Ks[nc + g][kk + tg];
                bfr[1] = Ks[nc + g][kk + tg + 4];
                mma_f16(s[nt], qfr[ks], bfr);
            }
        }

        // ---- scale + causal mask (registers) ----
        const bool dm = (kt >= 2 * qi);
#pragma unroll
        for (int nt = 0; nt < 8; nt++) {
            const int c0 = k0 + nt * 8 + 2 * tg;
            s[nt][0] *= 0.125f; s[nt][1] *= 0.125f;
            s[nt][2] *= 0.125f; s[nt][3] *= 0.125f;
            if (dm) {
                if (c0 > row0g)     s[nt][0] = -1e30f;
                if (c0 + 1 > row0g) s[nt][1] = -1e30f;
                if (c0 > row1g)     s[nt][2] = -1e30f;
                if (c0 + 1 > row1g) s[nt][3] = -1e30f;
            }
        }

        // ---- in-register online softmax (quad shuffles) ----
        float mt0 = -1e30f, mt1 = -1e30f;
#pragma unroll
        for (int nt = 0; nt < 8; nt++) {
            mt0 = fmaxf(mt0, fmaxf(s[nt][0], s[nt][1]));
            mt1 = fmaxf(mt1, fmaxf(s[nt][2], s[nt][3]));
        }
        mt0 = fmaxf(mt0, __shfl_xor_sync(0xffffffffu, mt0, 1));
        mt0 = fmaxf(mt0, __shfl_xor_sync(0xffffffffu, mt0, 2));
        mt1 = fmaxf(mt1, __shfl_xor_sync(0xffffffffu, mt1, 1));
        mt1 = fmaxf(mt1, __shfl_xor_sync(0xffffffffu, mt1, 2));
        float mn0 = fmaxf(m0, mt0), mn1 = fmaxf(m1, mt1);
        float f0 = __expf(m0 - mn0), f1 = __expf(m1 - mn1);
        float ls0 = 0.0f, ls1 = 0.0f;
#pragma unroll
        for (int nt = 0; nt < 8; nt++) {
            s[nt][0] = __expf(s[nt][0] - mn0); ls0 += s[nt][0];
            s[nt][1] = __expf(s[nt][1] - mn0); ls0 += s[nt][1];
            s[nt][2] = __expf(s[nt][2] - mn1); ls1 += s[nt][2];
            s[nt][3] = __expf(s[nt][3] - mn1); ls1 += s[nt][3];
        }
        ls0 += __shfl_xor_sync(0xffffffffu, ls0, 1);
        ls0 += __shfl_xor_sync(0xffffffffu, ls0, 2);
        ls1 += __shfl_xor_sync(0xffffffffu, ls1, 1);
        ls1 += __shfl_xor_sync(0xffffffffu, ls1, 2);
        m0 = mn0; m1 = mn1;
        l0 = l0 * f0 + ls0;
        l1 = l1 * f1 + ls1;

        // ---- rescale O, pack P frags in-register, P @ V ----
#pragma unroll
        for (int nt = 0; nt < 8; nt++) {
            acc_o[nt][0] *= f0; acc_o[nt][1] *= f0;
            acc_o[nt][2] *= f1; acc_o[nt][3] *= f1;
        }
#pragma unroll
        for (int ts = 0; ts < 4; ts++) {
            uint32_t pfr[4];
            pfr[0] = packh2(s[2 * ts][0], s[2 * ts][1]);
            pfr[1] = packh2(s[2 * ts][2], s[2 * ts][3]);
            pfr[2] = packh2(s[2 * ts + 1][0], s[2 * ts + 1][1]);
            pfr[3] = packh2(s[2 * ts + 1][2], s[2 * ts + 1][3]);
#pragma unroll
            for (int nt = 0; nt < 8; nt++) {
                const int nc = nt * 8;
                uint32_t bfr[2];
                bfr[0] = Vp[ts * 8 + tg][nc + g];
                bfr[1] = Vp[ts * 8 + tg + 4][nc + g];
                mma_f16(acc_o[nt], pfr, bfr);
            }
        }
    }

    // ---- epilogue: normalize, write g_y (half) in [B,T,C] layout ----
    const int b = bh / 12, h = bh - b * 12;
    float inv0 = 1.0f / l0;
    float inv1 = 1.0f / l1;
    const int t0 = q0 + mr + g, t1 = t0 + 8;
#pragma unroll
    for (int nt = 0; nt < 8; nt++) {
        int col = nt * 8 + 2 * tg;   // even
        uint32_t* d0 = (uint32_t*)(g_y + ((size_t)(b * 1024 + t0)) * 768 + h * 64 + col);
        uint32_t* d1 = (uint32_t*)(g_y + ((size_t)(b * 1024 + t1)) * 768 + h * 64 + col);
        *d0 = packh2(acc_o[nt][0] * inv0, acc_o[nt][1] * inv0);
        *d1 = packh2(acc_o[nt][2] * inv1, acc_o[nt][3] * inv1);
    }
}

// ---------------------------------------------------------------------------
extern "C" void kernel_launch(void* const* d_in, const int* in_sizes, int n_in,
                              void* d_out, int out_size)
{
    const float* x      = (const float*)d_in[0];
    const float* w_attn = (const float*)d_in[1];
    const float* b_attn = (const float*)d_in[2];
    const float* w_proj = (const float*)d_in[3];
    const float* b_proj = (const float*)d_in[4];
    float* out = (float*)d_out;

    static bool attr_set = false;
    if (!attr_set) {
        cudaFuncSetAttribute(gemm_qkv_h,
            cudaFuncAttributeMaxDynamicSharedMemorySize, GEMM_SMEM_BYTES);
        cudaFuncSetAttribute(gemm_proj_h,
            cudaFuncAttributeMaxDynamicSharedMemorySize, GEMM_SMEM_BYTES);
        attr_set = true;
    }

    prep_kernel<<<10752, 256>>>(x, w_attn, w_proj);
    gemm_qkv_h<<<dim3(18, 64), 256, GEMM_SMEM_BYTES>>>(b_attn);
    attn_h_kernel<<<dim3(8, 96), 256>>>();
    gemm_proj_h<<<dim3(6, 64), 256, GEMM_SMEM_BYTES>>>(b_proj, out);
}